// round 14
// baseline (speedup 1.0000x reference)
#include <cuda_runtime.h>
#include <math.h>

#define MAXN 32768
#define NTHREADS 128
#define MAXBLOCKS 512

__device__ float g_part[MAXBLOCKS];
__device__ unsigned int g_count = 0;

// Jarvis gift-wrap of K points -> CCW hull vertex cycle.
// Fills hx/hy[0..h-1], returns h, and accumulates 2*signed area into *s2out.
template<int K>
__device__ __forceinline__ int wrap_hull(const float* x, const float* y,
                                         float* hx, float* hy, float* s2out) {
    int start = 0;
    #pragma unroll
    for (int k = 1; k < K; k++)
        if (y[k] < y[start] || (y[k] == y[start] && x[k] < x[start])) start = k;

    float s2 = 0.f;
    int h = 0, cur = start;
    for (int it = 0; it < K; it++) {
        hx[h] = x[cur]; hy[h] = y[cur]; h++;
        float cx = x[cur], cy = y[cur];
        int nxt = (cur == 0) ? 1 : 0;
        float ex = x[nxt] - cx, ey = y[nxt] - cy;
        #pragma unroll
        for (int c = 0; c < K; c++) {
            if (c == cur) continue;
            float cr = ex * (y[c] - cy) - ey * (x[c] - cx);
            if (cr < 0.f) { nxt = c; ex = x[c] - cx; ey = y[c] - cy; }
        }
        s2 += cx * y[nxt] - x[nxt] * cy;
        cur = nxt;
        if (cur == start) break;
    }
    *s2out = s2;
    return h;
}

// Area-only gift wrap (no vertex storage) for the pred+target hull.
template<int K>
__device__ __forceinline__ float wrap_area(const float* x, const float* y) {
    int start = 0;
    #pragma unroll
    for (int k = 1; k < K; k++)
        if (y[k] < y[start] || (y[k] == y[start] && x[k] < x[start])) start = k;

    float s2 = 0.f;
    int cur = start;
    for (int it = 0; it < K; it++) {
        float cx = x[cur], cy = y[cur];
        int nxt = (cur == 0) ? 1 : 0;
        float ex = x[nxt] - cx, ey = y[nxt] - cy;
        #pragma unroll
        for (int c = 0; c < K; c++) {
            if (c == cur) continue;
            float cr = ex * (y[c] - cy) - ey * (x[c] - cx);
            if (cr < 0.f) { nxt = c; ex = x[c] - cx; ey = y[c] - cy; }
        }
        s2 += cx * y[nxt] - x[nxt] * cy;
        cur = nxt;
        if (cur == start) break;
    }
    return 0.5f * fabsf(s2);
}

__global__ void __launch_bounds__(NTHREADS) giou_kernel(const float* __restrict__ pred,
                                                        const float* __restrict__ target,
                                                        const float* __restrict__ weight,
                                                        int n, int out_size,
                                                        float* __restrict__ out) {
    int i = blockIdx.x * blockDim.x + threadIdx.x;
    float loss = 0.f;

    if (i < n) {
        float Px[9], Py[9];
        const float2* p2 = (const float2*)(pred) + (size_t)i * 9;
        #pragma unroll
        for (int k = 0; k < 9; k++) {
            float2 v = p2[k];
            Px[k] = v.x; Py[k] = v.y;
        }
        float Tx[4], Ty[4];
        const float2* t2 = (const float2*)(target) + (size_t)i * 4;
        #pragma unroll
        for (int k = 0; k < 4; k++) {
            float2 v = t2[k];
            Tx[k] = v.x; Ty[k] = v.y;
        }

        // target signed area + CCW orientation
        float sa = 0.f;
        #pragma unroll
        for (int k = 0; k < 4; k++) {
            int j = (k + 1) & 3;
            sa += Tx[k] * Ty[j] - Tx[j] * Ty[k];
        }
        sa *= 0.5f;
        float Cx[4], Cy[4];
        #pragma unroll
        for (int k = 0; k < 4; k++) {
            int s = (sa < 0.f) ? (3 - k) : k;
            Cx[k] = Tx[s]; Cy[k] = Ty[s];
        }
        float areaB = fabsf(sa);

        // hull of pred (CCW cycle + area in one pass)
        float sx[16], sy[16], s2A;
        int m = wrap_hull<9>(Px, Py, sx, sy, &s2A);
        float areaA = 0.5f * fabsf(s2A);

        // Sutherland-Hodgman vs 4 CCW target edges, dynamic vertex count.
        for (int e = 0; e < 4 && m > 0; e++) {
            float ax = Cx[e], ay = Cy[e];
            int en = (e + 1) & 3;
            float ex = Cx[en] - ax, ey = Cy[en] - ay;

            float d[16];
            for (int k = 0; k < m; k++)
                d[k] = ex * (sy[k] - ay) - ey * (sx[k] - ax);

            float ox[16], oy[16];
            int mo = 0;
            for (int k = 0; k < m; k++) {
                int kn = (k + 1 == m) ? 0 : k + 1;
                float dp = d[k], dq = d[kn];
                bool ip = (dp >= 0.f), iq = (dq >= 0.f);
                if (ip != iq) {
                    float den = dp - dq;
                    float t = dp / ((fabsf(den) < 1e-9f) ? 1e-9f : den);
                    if (mo < 16) {
                        ox[mo] = sx[k] + t * (sx[kn] - sx[k]);
                        oy[mo] = sy[k] + t * (sy[kn] - sy[k]);
                        mo++;
                    }
                }
                if (iq && mo < 16) { ox[mo] = sx[kn]; oy[mo] = sy[kn]; mo++; }
            }
            for (int j = 0; j < mo; j++) { sx[j] = ox[j]; sy[j] = oy[j]; }
            m = mo;
        }

        float inter = 0.f;
        for (int k = 0; k < m; k++) {
            int j = (k + 1 == m) ? 0 : k + 1;
            inter += sx[k] * sy[j] - sx[j] * sy[k];
        }
        inter = 0.5f * fabsf(inter);
        inter = fminf(inter, fminf(areaA, areaB));   // firewall, no-op when sane

        // hull of pred+target (area only)
        float Ux[13], Uy[13];
        #pragma unroll
        for (int k = 0; k < 9; k++) { Ux[k] = Px[k]; Uy[k] = Py[k]; }
        #pragma unroll
        for (int k = 0; k < 4; k++) { Ux[9 + k] = Tx[k]; Uy[9 + k] = Ty[k]; }
        float areaC = wrap_area<13>(Ux, Uy);

        float uni  = areaA + areaB - inter;
        float giou = inter / fmaxf(uni, 1e-9f) - (areaC - uni) / fmaxf(areaC, 1e-9f);
        giou = fminf(fmaxf(giou, -1.f), 1.f);

        loss = (1.f - giou) * weight[i];
    }

    // deterministic per-block tree reduction
    __shared__ float sh[NTHREADS];
    sh[threadIdx.x] = loss;
    __syncthreads();
    #pragma unroll
    for (int st = NTHREADS / 2; st > 0; st >>= 1) {
        if (threadIdx.x < st) sh[threadIdx.x] += sh[threadIdx.x + st];
        __syncthreads();
    }

    __shared__ bool amLast;
    if (threadIdx.x == 0) {
        g_part[blockIdx.x] = sh[0];
        __threadfence();
        unsigned int ticket = atomicAdd(&g_count, 1u);
        amLast = (ticket == gridDim.x - 1);
    }
    __syncthreads();

    // Last block to finish performs the final reduction in a FIXED order
    // (independent of arrival order -> deterministic output).
    if (amLast) {
        int t = threadIdx.x;
        double s = 0.0;
        for (int b = t; b < (int)gridDim.x; b += NTHREADS)
            s += (double)g_part[b];
        __shared__ double dsh[NTHREADS];
        dsh[t] = s;
        __syncthreads();
        #pragma unroll
        for (int st = NTHREADS / 2; st > 0; st >>= 1) {
            if (t < st) dsh[t] += dsh[t + st];
            __syncthreads();
        }
        if (t == 0) {
            float mean = (float)(dsh[0] / (double)n);
            for (int j = 0; j < out_size; j++) out[j] = mean;
            g_count = 0;   // reset for next graph replay
        }
    }
}

extern "C" void kernel_launch(void* const* d_in, const int* in_sizes, int n_in,
                              void* d_out, int out_size) {
    // Map inputs by element count: pred=18n (largest), target=8n, weight=n (smallest).
    int mx = 0, mn = 0;
    for (int k = 1; k < n_in; k++) {
        if (in_sizes[k] > in_sizes[mx]) mx = k;
        if (in_sizes[k] < in_sizes[mn]) mn = k;
    }
    int ip = mx, iw = mn, it = 0;
    for (int k = 0; k < n_in; k++)
        if (k != ip && k != iw) { it = k; break; }

    const float* pred   = (const float*)d_in[ip];
    const float* target = (const float*)d_in[it];
    const float* weight = (const float*)d_in[iw];
    float* out = (float*)d_out;

    int n = in_sizes[iw];
    if (n > MAXN) n = MAXN;

    int blocks = (n + NTHREADS - 1) / NTHREADS;   // 256 for n=32768
    if (blocks > MAXBLOCKS) blocks = MAXBLOCKS;
    giou_kernel<<<blocks, NTHREADS>>>(pred, target, weight, n, out_size, out);
}

// round 15
// speedup vs baseline: 1.3034x; 1.3034x over previous
#include <cuda_runtime.h>
#include <math.h>

#define MAXN 32768
#define TPB 256
#define EPB 128              // elements per block (role A = warps 0-3, role B = warps 4-7)
#define MAXBLOCKS 512

__device__ float g_part[MAXBLOCKS];
__device__ unsigned int g_count = 0;

// Jarvis gift-wrap of K points -> CCW hull cycle into hx/hy, returns count,
// accumulates 2*signed area into *s2out.
template<int K>
__device__ __forceinline__ int wrap_hull(const float* x, const float* y,
                                         float* hx, float* hy, float* s2out) {
    int start = 0;
    #pragma unroll
    for (int k = 1; k < K; k++)
        if (y[k] < y[start] || (y[k] == y[start] && x[k] < x[start])) start = k;

    float s2 = 0.f;
    int h = 0, cur = start;
    for (int it = 0; it < K; it++) {
        hx[h] = x[cur]; hy[h] = y[cur]; h++;
        float cx = x[cur], cy = y[cur];
        int nxt = (cur == 0) ? 1 : 0;
        float ex = x[nxt] - cx, ey = y[nxt] - cy;
        #pragma unroll
        for (int c = 0; c < K; c++) {
            if (c == cur) continue;
            float cr = ex * (y[c] - cy) - ey * (x[c] - cx);
            if (cr < 0.f) { nxt = c; ex = x[c] - cx; ey = y[c] - cy; }
        }
        s2 += cx * y[nxt] - x[nxt] * cy;
        cur = nxt;
        if (cur == start) break;
    }
    *s2out = s2;
    return h;
}

// Area-only gift wrap for the pred+target hull (no vertex storage).
template<int K>
__device__ __forceinline__ float wrap_area(const float* x, const float* y) {
    int start = 0;
    #pragma unroll
    for (int k = 1; k < K; k++)
        if (y[k] < y[start] || (y[k] == y[start] && x[k] < x[start])) start = k;

    float s2 = 0.f;
    int cur = start;
    for (int it = 0; it < K; it++) {
        float cx = x[cur], cy = y[cur];
        int nxt = (cur == 0) ? 1 : 0;
        float ex = x[nxt] - cx, ey = y[nxt] - cy;
        #pragma unroll
        for (int c = 0; c < K; c++) {
            if (c == cur) continue;
            float cr = ex * (y[c] - cy) - ey * (x[c] - cx);
            if (cr < 0.f) { nxt = c; ex = x[c] - cx; ey = y[c] - cy; }
        }
        s2 += cx * y[nxt] - x[nxt] * cy;
        cur = nxt;
        if (cur == start) break;
    }
    return 0.5f * fabsf(s2);
}

__global__ void __launch_bounds__(TPB) giou_kernel(const float* __restrict__ pred,
                                                   const float* __restrict__ target,
                                                   const float* __restrict__ weight,
                                                   int n, int out_size,
                                                   float* __restrict__ out) {
    int tid  = threadIdx.x;
    int role = tid >> 7;           // 0: hullA+clip+inter, 1: areaC
    int lane = tid & (EPB - 1);
    int i    = blockIdx.x * EPB + lane;
    bool valid = (i < n);

    __shared__ float s_areaC[EPB];
    __shared__ float s_loss[EPB];

    float inter = 0.f, areaA = 0.f, areaB = 0.f, w = 0.f;

    if (role == 1) {
        // ---- role B: hull of pred+target, area only ----
        float aC = 0.f;
        if (valid) {
            float Ux[13], Uy[13];
            const float2* p2 = (const float2*)(pred) + (size_t)i * 9;
            #pragma unroll
            for (int k = 0; k < 9; k++) { float2 v = p2[k]; Ux[k] = v.x; Uy[k] = v.y; }
            const float2* t2 = (const float2*)(target) + (size_t)i * 4;
            #pragma unroll
            for (int k = 0; k < 4; k++) { float2 v = t2[k]; Ux[9 + k] = v.x; Uy[9 + k] = v.y; }
            aC = wrap_area<13>(Ux, Uy);
        }
        s_areaC[lane] = aC;
    } else if (valid) {
        // ---- role A: hull of pred, clip vs target, intersection area ----
        float Px[9], Py[9];
        const float2* p2 = (const float2*)(pred) + (size_t)i * 9;
        #pragma unroll
        for (int k = 0; k < 9; k++) { float2 v = p2[k]; Px[k] = v.x; Py[k] = v.y; }
        float Tx[4], Ty[4];
        const float2* t2 = (const float2*)(target) + (size_t)i * 4;
        #pragma unroll
        for (int k = 0; k < 4; k++) { float2 v = t2[k]; Tx[k] = v.x; Ty[k] = v.y; }

        w = weight[i];

        float sa = 0.f;
        #pragma unroll
        for (int k = 0; k < 4; k++) {
            int j = (k + 1) & 3;
            sa += Tx[k] * Ty[j] - Tx[j] * Ty[k];
        }
        sa *= 0.5f;
        float Cx[4], Cy[4];
        #pragma unroll
        for (int k = 0; k < 4; k++) {
            int s = (sa < 0.f) ? (3 - k) : k;
            Cx[k] = Tx[s]; Cy[k] = Ty[s];
        }
        areaB = fabsf(sa);

        float sx[16], sy[16], s2A;
        int m = wrap_hull<9>(Px, Py, sx, sy, &s2A);
        areaA = 0.5f * fabsf(s2A);

        for (int e = 0; e < 4 && m > 0; e++) {
            float ax = Cx[e], ay = Cy[e];
            int en = (e + 1) & 3;
            float ex = Cx[en] - ax, ey = Cy[en] - ay;

            float ox[16], oy[16];
            int mo = 0;
            float d0 = ex * (sy[0] - ay) - ey * (sx[0] - ax);
            float dc = d0;
            for (int k = 0; k < m; k++) {
                int kn = (k + 1 == m) ? 0 : k + 1;
                float dn = (kn == 0) ? d0
                         : ex * (sy[kn] - ay) - ey * (sx[kn] - ax);
                bool ip = (dc >= 0.f), iq = (dn >= 0.f);
                if (ip != iq) {
                    float den = dc - dn;
                    float t = dc / ((fabsf(den) < 1e-9f) ? 1e-9f : den);
                    if (mo < 16) {
                        ox[mo] = sx[k] + t * (sx[kn] - sx[k]);
                        oy[mo] = sy[k] + t * (sy[kn] - sy[k]);
                        mo++;
                    }
                }
                if (iq && mo < 16) { ox[mo] = sx[kn]; oy[mo] = sy[kn]; mo++; }
                dc = dn;
            }
            for (int j = 0; j < mo; j++) { sx[j] = ox[j]; sy[j] = oy[j]; }
            m = mo;
        }

        float is = 0.f;
        for (int k = 0; k < m; k++) {
            int j = (k + 1 == m) ? 0 : k + 1;
            is += sx[k] * sy[j] - sx[j] * sy[k];
        }
        inter = 0.5f * fabsf(is);
        inter = fminf(inter, fminf(areaA, areaB));   // firewall, no-op when sane
    }
    __syncthreads();

    // ---- role A combines with role B's areaC ----
    if (role == 0) {
        float loss = 0.f;
        if (valid) {
            float areaC = s_areaC[lane];
            float uni   = areaA + areaB - inter;
            float giou  = inter / fmaxf(uni, 1e-9f) - (areaC - uni) / fmaxf(areaC, 1e-9f);
            giou = fminf(fmaxf(giou, -1.f), 1.f);
            loss = (1.f - giou) * w;
        }
        s_loss[lane] = loss;
    }
    __syncthreads();

    // deterministic block tree reduction over 128 losses
    #pragma unroll
    for (int st = EPB / 2; st > 0; st >>= 1) {
        if (tid < st) s_loss[tid] += s_loss[tid + st];
        __syncthreads();
    }

    __shared__ bool amLast;
    if (tid == 0) {
        g_part[blockIdx.x] = s_loss[0];
        __threadfence();
        unsigned int ticket = atomicAdd(&g_count, 1u);
        amLast = (ticket == gridDim.x - 1);
    }
    __syncthreads();

    // Last block: final fixed-order reduction (deterministic).
    if (amLast) {
        double s = 0.0;
        for (int b = tid; b < (int)gridDim.x; b += TPB)
            s += (double)g_part[b];
        __shared__ double dsh[TPB];
        dsh[tid] = s;
        __syncthreads();
        #pragma unroll
        for (int st = TPB / 2; st > 0; st >>= 1) {
            if (tid < st) dsh[tid] += dsh[tid + st];
            __syncthreads();
        }
        if (tid == 0) {
            float mean = (float)(dsh[0] / (double)n);
            for (int j = 0; j < out_size; j++) out[j] = mean;
            g_count = 0;   // reset for next graph replay
        }
    }
}

extern "C" void kernel_launch(void* const* d_in, const int* in_sizes, int n_in,
                              void* d_out, int out_size) {
    // Map inputs by element count: pred=18n (largest), target=8n, weight=n (smallest).
    int mx = 0, mn = 0;
    for (int k = 1; k < n_in; k++) {
        if (in_sizes[k] > in_sizes[mx]) mx = k;
        if (in_sizes[k] < in_sizes[mn]) mn = k;
    }
    int ip = mx, iw = mn, it = 0;
    for (int k = 0; k < n_in; k++)
        if (k != ip && k != iw) { it = k; break; }

    const float* pred   = (const float*)d_in[ip];
    const float* target = (const float*)d_in[it];
    const float* weight = (const float*)d_in[iw];
    float* out = (float*)d_out;

    int n = in_sizes[iw];
    if (n > MAXN) n = MAXN;

    int blocks = (n + EPB - 1) / EPB;    // 256 for n=32768
    if (blocks > MAXBLOCKS) blocks = MAXBLOCKS;
    giou_kernel<<<blocks, TPB>>>(pred, target, weight, n, out_size, out);
}